// round 1
// baseline (speedup 1.0000x reference)
#include <cuda_runtime.h>
#include <cuda_bf16.h>

#define T_ 8
#define H_ 64
#define W_ 64
#define C_ 64
#define HW_ (H_*W_)
#define THW_ (T_*HW_)

// ---------------- device scratch (allocation-free rule) ----------------
__device__ float g_y1[C_*THW_];        // lrelu(conv1) output, 8 MB
__device__ float g_off[54*THW_];       // offset conv output, 7 MB
__device__ float g_wdt[27*64*64];      // Wd transposed to [k][c][o]

// ---------------- 3x3x3 conv, Cin=64, pad=1, optional LReLU ----------------
// block handles (t, 8x8 spatial tile); 256 threads = 64 cout x 4 row-groups;
// each thread accumulates 2 rows x 8 w = 16 outputs for its cout.
template<int COUT, bool LRELU, bool FROM_Y1, bool TO_OFF>
__global__ __launch_bounds__(256)
void conv3x3x3(const float* __restrict__ xin, const float* __restrict__ w,
               const float* __restrict__ b)
{
    __shared__ float xs[3][10][10];
    __shared__ float ws[COUT*27];

    const float* x = FROM_Y1 ? g_y1 : xin;
    float* y = TO_OFF ? g_off : g_y1;

    int t  = blockIdx.z;
    int h0 = blockIdx.y * 8;
    int w0 = blockIdx.x * 8;
    int tid = threadIdx.x;
    int co = tid & 63;
    int sg = tid >> 6;

    float acc[16];
    #pragma unroll
    for (int i = 0; i < 16; i++) acc[i] = 0.f;

    for (int ci = 0; ci < C_; ci++) {
        // stage input patch with zero padding (3t x 10h x 10w)
        for (int i = tid; i < 300; i += 256) {
            int dt = i / 100, rem = i % 100;
            int r = rem / 10, c = rem % 10;
            int tt = t + dt - 1, hh = h0 + r - 1, ww = w0 + c - 1;
            float v = 0.f;
            if (tt >= 0 && tt < T_ && hh >= 0 && hh < H_ && ww >= 0 && ww < W_)
                v = x[ci*THW_ + tt*HW_ + hh*W_ + ww];
            xs[dt][r][c] = v;
        }
        // stage weights for this cin (stride-27 smem reads are bank-conflict-free)
        for (int i = tid; i < COUT*27; i += 256)
            ws[i] = w[(i/27)*(C_*27) + ci*27 + (i%27)];
        __syncthreads();

        if (co < COUT) {
            float wr[27];
            #pragma unroll
            for (int j = 0; j < 27; j++) wr[j] = ws[co*27 + j];

            #pragma unroll
            for (int r2 = 0; r2 < 2; r2++) {
                int orow = sg*2 + r2;
                #pragma unroll
                for (int kt = 0; kt < 3; kt++)
                #pragma unroll
                for (int kh = 0; kh < 3; kh++) {
                    float xrow[10];
                    #pragma unroll
                    for (int cc = 0; cc < 10; cc++) xrow[cc] = xs[kt][orow+kh][cc];
                    #pragma unroll
                    for (int ww2 = 0; ww2 < 8; ww2++) {
                        #pragma unroll
                        for (int kw = 0; kw < 3; kw++)
                            acc[r2*8 + ww2] += wr[(kt*3+kh)*3 + kw] * xrow[ww2 + kw];
                    }
                }
            }
        }
        __syncthreads();
    }

    if (co < COUT) {
        float bb = __ldg(&b[co]);
        #pragma unroll
        for (int r2 = 0; r2 < 2; r2++) {
            int orow = sg*2 + r2;
            #pragma unroll
            for (int ww2 = 0; ww2 < 8; ww2++) {
                float v = acc[r2*8 + ww2] + bb;
                if (LRELU) v = (v >= 0.f) ? v : 0.01f*v;
                y[co*THW_ + t*HW_ + (h0+orow)*W_ + (w0+ww2)] = v;
            }
        }
    }
}

// ---------------- Wd transpose: (O,C,27) -> [k][c][o] ----------------
__global__ void transpose_wd(const float* __restrict__ wd)
{
    int i = blockIdx.x * 256 + threadIdx.x;
    if (i < 27*64*64) {
        int k = i / 4096;
        int rem = i % 4096;
        int c = rem / 64;
        int o = rem % 64;
        g_wdt[i] = wd[(o*64 + c)*27 + k];
    }
}

// ---------------- residual 1x1x1 conv: writes base value into out ----------------
__global__ __launch_bounds__(256)
void res1x1(const float* __restrict__ x, const float* __restrict__ wr,
            const float* __restrict__ br, float* __restrict__ out)
{
    __shared__ float ws[64*64];
    int tid = threadIdx.x;
    for (int i = tid; i < 4096; i += 256) ws[i] = wr[i];
    __syncthreads();

    int s = blockIdx.x * 256 + tid;
    float acc[64];
    #pragma unroll
    for (int o = 0; o < 64; o++) acc[o] = __ldg(&br[o]);
    for (int c = 0; c < 64; c++) {
        float xv = x[c*THW_ + s];
        #pragma unroll
        for (int o = 0; o < 64; o++) acc[o] += ws[o*64 + c] * xv;
    }
    #pragma unroll
    for (int o = 0; o < 64; o++) out[o*THW_ + s] = acc[o];
}

// ---------------- deformable conv (HW offsets) + LReLU + residual add ----------------
// block handles (t, h, 32 consecutive w). 256 threads.
// Per k-tap: bilinear idx/weights -> cols[c][sp] via gathers -> 64x64 GEMM step.
__global__ __launch_bounds__(256)
void deform_k(const float* __restrict__ bd, float* __restrict__ out)
{
    __shared__ int   gidx[32][4];
    __shared__ float gwgt[32][4];
    __shared__ float cols[64*32];
    __shared__ float wds[64*64];

    int t = blockIdx.z, h = blockIdx.y, w0 = blockIdx.x * 32;
    int tid = threadIdx.x;
    int co = tid & 63, sg = tid >> 6;
    int sbase = t*HW_ + h*W_ + w0;

    float acc[8];
    #pragma unroll
    for (int j = 0; j < 8; j++) acc[j] = 0.f;

    for (int k = 0; k < 27; k++) {
        int kt = k / 9, kh = (k / 3) % 3, kw = k % 3;
        int t_in = t - 1 + kt;
        bool t_ok = (t_in >= 0) && (t_in < T_);
        int t_c = min(max(t_in, 0), T_-1);

        if (tid < 128) {
            int sp = tid >> 2, cor = tid & 3;
            int wpos = w0 + sp;
            float dh = g_off[(2*k + 0)*THW_ + sbase + sp];
            float dw = g_off[(2*k + 1)*THW_ + sbase + sp];
            float h_s = (float)(h - 1 + kh) + dh;
            float w_s = (float)(wpos - 1 + kw) + dw;
            float h0f = floorf(h_s), w0f = floorf(w_s);
            float fh = h_s - h0f, fw = w_s - w0f;
            int ih = (int)h0f + (cor >> 1);
            int iw = (int)w0f + (cor & 1);
            float wh = (cor >> 1) ? fh : 1.f - fh;
            float wv = (cor & 1)  ? fw : 1.f - fw;
            bool ok = t_ok && ih >= 0 && ih < H_ && iw >= 0 && iw < W_;
            int ihc = min(max(ih, 0), H_-1);
            int iwc = min(max(iw, 0), W_-1);
            gidx[sp][cor] = t_c*HW_ + ihc*W_ + iwc;
            gwgt[sp][cor] = ok ? wh*wv : 0.f;
        }
        // stage this tap's weights, layout wds[c*64+o] (coalesced global, conflict-free smem)
        for (int i = tid; i < 4096; i += 256) wds[i] = g_wdt[k*4096 + i];
        __syncthreads();

        // phase A: cols[c][sp] via 4-tap bilinear gathers from y1
        {
            int sp = tid & 31;
            int cb = tid >> 5;   // 0..7
            int i0 = gidx[sp][0], i1 = gidx[sp][1], i2 = gidx[sp][2], i3 = gidx[sp][3];
            float q0 = gwgt[sp][0], q1 = gwgt[sp][1], q2 = gwgt[sp][2], q3 = gwgt[sp][3];
            #pragma unroll
            for (int j = 0; j < 8; j++) {
                int c = cb*8 + j;
                const float* p = g_y1 + c*THW_;
                cols[c*32 + sp] = q0*p[i0] + q1*p[i1] + q2*p[i2] + q3*p[i3];
            }
        }
        __syncthreads();

        // phase B: acc[sp0..7 for cout co] += wd[o][c][k] * cols[c][sp]
        {
            const float* cbase = &cols[sg*8];
            #pragma unroll 8
            for (int c = 0; c < 64; c++) {
                float wv = wds[c*64 + co];
                const float* cp = cbase + c*32;
                #pragma unroll
                for (int j = 0; j < 8; j++) acc[j] += wv * cp[j];
            }
        }
        __syncthreads();
    }

    float bb = __ldg(&bd[co]);
    #pragma unroll
    for (int j = 0; j < 8; j++) {
        int idx = co*THW_ + sbase + sg*8 + j;
        float v = acc[j] + bb;
        v = (v >= 0.f) ? v : 0.01f*v;
        out[idx] = v + out[idx];
    }
}

// ---------------- launch ----------------
extern "C" void kernel_launch(void* const* d_in, const int* in_sizes, int n_in,
                              void* d_out, int out_size)
{
    const float* x     = (const float*)d_in[0];
    const float* W1    = (const float*)d_in[1];
    const float* b1    = (const float*)d_in[2];
    const float* W_off = (const float*)d_in[3];
    const float* b_off = (const float*)d_in[4];
    const float* Wd    = (const float*)d_in[5];
    const float* bd    = (const float*)d_in[6];
    const float* Wr    = (const float*)d_in[7];
    const float* br    = (const float*)d_in[8];
    float* out = (float*)d_out;
    (void)in_sizes; (void)n_in; (void)out_size;

    dim3 cgrid(8, 8, 8);  // (w-tiles, h-tiles, t)

    // y1 = lrelu(conv3d(x, W1, b1, pad=1))        -> g_y1
    conv3x3x3<64, true,  false, false><<<cgrid, 256>>>(x, W1, b1);
    // offsets = conv3d(y1, W_off, b_off, pad=1)   -> g_off
    conv3x3x3<54, false, true,  true ><<<cgrid, 256>>>(nullptr, W_off, b_off);
    // weight reorder for the deform GEMM
    transpose_wd<<<(27*64*64 + 255)/256, 256>>>(Wd);
    // residual base: out = conv1x1(x, Wr) + br
    res1x1<<<THW_/256, 256>>>(x, Wr, br, out);
    // out += lrelu(deform(y1, offsets) + bd)
    deform_k<<<dim3(2, 64, 8), 256>>>(bd, out);
}

// round 2
// speedup vs baseline: 1.1427x; 1.1427x over previous
#include <cuda_runtime.h>

#define T_ 8
#define H_ 64
#define W_ 64
#define C_ 64
#define HW_ (H_*W_)
#define THW_ (T_*HW_)

typedef unsigned long long u64;

// ---------------- packed fp32x2 helpers (Blackwell FFMA2) ----------------
__device__ __forceinline__ void fma2(u64& acc, u64 a, u64 b){
    asm("fma.rn.f32x2 %0, %1, %2, %0;" : "+l"(acc) : "l"(a), "l"(b));
}
__device__ __forceinline__ u64 pack2(float x, float y){
    u64 r; asm("mov.b64 %0, {%1, %2};" : "=l"(r) : "f"(x), "f"(y)); return r;
}
__device__ __forceinline__ float2 unpack2(u64 v){
    float2 r; asm("mov.b64 {%0, %1}, %2;" : "=f"(r.x), "=f"(r.y) : "l"(v)); return r;
}

// ---------------- device scratch (allocation-free rule) ----------------
__device__ float g_y1[C_*THW_];         // lrelu(conv1) output
__device__ float g_off[54*THW_];        // offset conv output
__device__ float g_w1t[64*27*64];       // W1    -> [ci][j][co]
__device__ float g_wofft[64*27*64];     // W_off -> [ci][j][co], co padded 54->64 w/ zeros
__device__ float g_wdt[27*64*64];       // Wd    -> [k][c][o]
__device__ float g_wrt[64*64];          // Wr    -> [c][o]

// ---------------- weight reorder (coalesced staging layouts) ----------------
__global__ void prep_weights(const float* __restrict__ W1, const float* __restrict__ Woff,
                             const float* __restrict__ Wd, const float* __restrict__ Wr)
{
    int i = blockIdx.x*256 + threadIdx.x;
    if (i < 110592) {
        int ci = i/(27*64); int r = i%(27*64); int j = r/64; int co = r%64;
        g_w1t[i] = W1[co*1728 + ci*27 + j];
    } else if (i < 221184) {
        int e = i-110592; int ci = e/(27*64); int r = e%(27*64); int j = r/64; int co = r%64;
        g_wofft[e] = (co < 54) ? Woff[co*1728 + ci*27 + j] : 0.f;
    } else if (i < 331776) {
        int e = i-221184; int k = e/4096; int r = e%4096; int c = r/64; int o = r%64;
        g_wdt[e] = Wd[(o*64+c)*27 + k];
    } else if (i < 335872) {
        int e = i-331776; int c = e/64; int o = e%64;
        g_wrt[e] = Wr[o*64 + c];
    }
}

// ---------------- 3x3x3 conv, Cin=64, pad=1, optional LReLU, f32x2 over cout pairs --------
// block: (t, 8h x 8w tile); 256 threads = 32 cout-pairs x 8 rows.
// Each thread: 2 couts x 1 row x 8 w -> acc2[8] packed pairs.
template<int COUT, bool LRELU, bool FROM_Y1, bool TO_OFF>
__global__ __launch_bounds__(256)
void conv3x3x3(const float* __restrict__ xin, const float* __restrict__ b)
{
    __shared__ u64 xs2[3][10][10];   // dup-packed (v,v) input patch
    __shared__ u64 ws2[27][32];      // (w[2cp], w[2cp+1]) per tap

    const float* x  = FROM_Y1 ? g_y1 : xin;
    const float* wt = TO_OFF ? g_wofft : g_w1t;
    float* y        = TO_OFF ? g_off : g_y1;

    int t  = blockIdx.z;
    int h0 = blockIdx.y * 8;
    int w0 = blockIdx.x * 8;
    int tid = threadIdx.x;
    int cp = tid & 31;        // cout pair
    int sg = tid >> 5;        // output row 0..7

    u64 acc[8];
    #pragma unroll
    for (int i = 0; i < 8; i++) acc[i] = 0ull;

    for (int ci = 0; ci < C_; ci++) {
        // stage input patch with zero padding (3t x 10h x 10w), dup-packed
        for (int i = tid; i < 300; i += 256) {
            int dt = i / 100, rem = i % 100;
            int r = rem / 10, c = rem % 10;
            int tt = t + dt - 1, hh = h0 + r - 1, ww = w0 + c - 1;
            float v = 0.f;
            if (tt >= 0 && tt < T_ && hh >= 0 && hh < H_ && ww >= 0 && ww < W_)
                v = x[ci*THW_ + tt*HW_ + hh*W_ + ww];
            xs2[dt][r][c] = pack2(v, v);
        }
        // stage weights: ws2[j][q] = (wt[ci][j][2q], wt[ci][j][2q+1]) — coalesced float2
        for (int e = tid; e < 864; e += 256) {
            int j = e >> 5, q = e & 31;
            float2 wv = *reinterpret_cast<const float2*>(&wt[ci*1728 + j*64 + 2*q]);
            ws2[j][q] = pack2(wv.x, wv.y);
        }
        __syncthreads();

        #pragma unroll
        for (int kt = 0; kt < 3; kt++) {
            #pragma unroll
            for (int kh = 0; kh < 3; kh++) {
                const ulonglong2* xp =
                    reinterpret_cast<const ulonglong2*>(&xs2[kt][sg + kh][0]);
                ulonglong2 v0 = xp[0], v1 = xp[1], v2 = xp[2], v3 = xp[3], v4 = xp[4];
                u64 xr[10] = {v0.x,v0.y,v1.x,v1.y,v2.x,v2.y,v3.x,v3.y,v4.x,v4.y};
                int j0 = (kt*3 + kh)*3;
                u64 wa = ws2[j0+0][cp], wb = ws2[j0+1][cp], wc = ws2[j0+2][cp];
                #pragma unroll
                for (int w = 0; w < 8; w++) {
                    fma2(acc[w], wa, xr[w]);
                    fma2(acc[w], wb, xr[w+1]);
                    fma2(acc[w], wc, xr[w+2]);
                }
            }
        }
        __syncthreads();
    }

    int co0 = 2*cp, co1 = 2*cp + 1;
    float b0 = (co0 < COUT) ? __ldg(&b[co0]) : 0.f;
    float b1 = (co1 < COUT) ? __ldg(&b[co1]) : 0.f;
    float out0[8], out1[8];
    #pragma unroll
    for (int w = 0; w < 8; w++) {
        float2 v = unpack2(acc[w]);
        float a0 = v.x + b0, a1 = v.y + b1;
        if (LRELU) { a0 = (a0 >= 0.f) ? a0 : 0.01f*a0;
                     a1 = (a1 >= 0.f) ? a1 : 0.01f*a1; }
        out0[w] = a0; out1[w] = a1;
    }
    int base = t*HW_ + (h0 + sg)*W_ + w0;
    if (co0 < COUT) {
        float4* p = reinterpret_cast<float4*>(&y[co0*THW_ + base]);
        p[0] = make_float4(out0[0], out0[1], out0[2], out0[3]);
        p[1] = make_float4(out0[4], out0[5], out0[6], out0[7]);
    }
    if (co1 < COUT) {
        float4* p = reinterpret_cast<float4*>(&y[co1*THW_ + base]);
        p[0] = make_float4(out1[0], out1[1], out1[2], out1[3]);
        p[1] = make_float4(out1[4], out1[5], out1[6], out1[7]);
    }
}

// ---------------- deformable conv + LReLU + fused residual, f32x2 over sp pairs ----------
// block: (h, t), full 64-wide row. 256 threads = 64 cout x 4 sp-groups (16 sp each).
__global__ __launch_bounds__(256)
void deform_fused(const float* __restrict__ x, const float* __restrict__ bd,
                  const float* __restrict__ br, float* __restrict__ out)
{
    __shared__ float  cols[64*64];
    __shared__ float  wds[64*64];
    __shared__ int4   gidx[64];
    __shared__ float4 gwgt[64];

    int h = blockIdx.x, t = blockIdx.y;
    int tid = threadIdx.x;
    int co = tid & 63, sg = tid >> 6;
    int sbase = t*HW_ + h*W_;

    u64 acc[8];
    #pragma unroll
    for (int i = 0; i < 8; i++) acc[i] = 0ull;

    for (int k = 0; k < 27; k++) {
        // phase 0: bilinear corner indices/weights for the 64 sp of this row
        if (tid < 64) {
            int sp = tid;
            float dh = g_off[(2*k + 0)*THW_ + sbase + sp];
            float dw = g_off[(2*k + 1)*THW_ + sbase + sp];
            int kt = k/9, kh = (k/3)%3, kw = k%3;
            int t_in = t - 1 + kt;
            bool t_ok = (t_in >= 0) && (t_in < T_);
            int t_c = min(max(t_in, 0), T_-1);
            float h_s = (float)(h - 1 + kh) + dh;
            float w_s = (float)(sp - 1 + kw) + dw;
            float h0f = floorf(h_s), w0f = floorf(w_s);
            float fh = h_s - h0f, fw = w_s - w0f;
            int ih0 = (int)h0f, iw0 = (int)w0f, ih1 = ih0+1, iw1 = iw0+1;
            bool okh0 = (ih0 >= 0) && (ih0 < H_), okh1 = (ih1 >= 0) && (ih1 < H_);
            bool okw0 = (iw0 >= 0) && (iw0 < W_), okw1 = (iw1 >= 0) && (iw1 < W_);
            int ih0c = min(max(ih0,0),H_-1), ih1c = min(max(ih1,0),H_-1);
            int iw0c = min(max(iw0,0),W_-1), iw1c = min(max(iw1,0),W_-1);
            int tb = t_c*HW_;
            gidx[sp] = make_int4(tb + ih0c*W_ + iw0c, tb + ih0c*W_ + iw1c,
                                 tb + ih1c*W_ + iw0c, tb + ih1c*W_ + iw1c);
            float wh0 = 1.f - fh, wh1 = fh, wv0 = 1.f - fw, wv1 = fw;
            gwgt[sp] = make_float4((t_ok && okh0 && okw0) ? wh0*wv0 : 0.f,
                                   (t_ok && okh0 && okw1) ? wh0*wv1 : 0.f,
                                   (t_ok && okh1 && okw0) ? wh1*wv0 : 0.f,
                                   (t_ok && okh1 && okw1) ? wh1*wv1 : 0.f);
        }
        // stage this tap's weights [c][o]
        #pragma unroll
        for (int r = 0; r < 16; r++)
            wds[r*256 + tid] = g_wdt[k*4096 + r*256 + tid];
        __syncthreads();

        // phase A: bilinear gathers -> cols[c][sp]
        #pragma unroll
        for (int r = 0; r < 16; r++) {
            int idx = r*256 + tid;
            int c = idx >> 6, sp = idx & 63;
            int4 gi = gidx[sp]; float4 gw = gwgt[sp];
            const float* p = g_y1 + c*THW_;
            cols[idx] = gw.x*p[gi.x] + gw.y*p[gi.y] + gw.z*p[gi.z] + gw.w*p[gi.w];
        }
        __syncthreads();

        // phase B: acc[co][sp pairs] += w[c][co] * cols[c][sp]
        #pragma unroll 8
        for (int c = 0; c < 64; c++) {
            float wv = wds[c*64 + co];
            u64 wp = pack2(wv, wv);
            const ulonglong2* cp2 =
                reinterpret_cast<const ulonglong2*>(&cols[c*64 + sg*16]);
            ulonglong2 q0 = cp2[0], q1 = cp2[1], q2 = cp2[2], q3 = cp2[3];
            fma2(acc[0], wp, q0.x); fma2(acc[1], wp, q0.y);
            fma2(acc[2], wp, q1.x); fma2(acc[3], wp, q1.y);
            fma2(acc[4], wp, q2.x); fma2(acc[5], wp, q2.y);
            fma2(acc[6], wp, q3.x); fma2(acc[7], wp, q3.y);
        }
        __syncthreads();
    }

    // fused residual: one extra GEMM step with x tile and Wr
    #pragma unroll
    for (int r = 0; r < 16; r++) {
        int idx = r*256 + tid;
        cols[idx] = x[(idx >> 6)*THW_ + sbase + (idx & 63)];
        wds[idx] = g_wrt[idx];
    }
    __syncthreads();
    u64 racc[8];
    #pragma unroll
    for (int i = 0; i < 8; i++) racc[i] = 0ull;
    #pragma unroll 8
    for (int c = 0; c < 64; c++) {
        float wv = wds[c*64 + co];
        u64 wp = pack2(wv, wv);
        const ulonglong2* cp2 =
            reinterpret_cast<const ulonglong2*>(&cols[c*64 + sg*16]);
        ulonglong2 q0 = cp2[0], q1 = cp2[1], q2 = cp2[2], q3 = cp2[3];
        fma2(racc[0], wp, q0.x); fma2(racc[1], wp, q0.y);
        fma2(racc[2], wp, q1.x); fma2(racc[3], wp, q1.y);
        fma2(racc[4], wp, q2.x); fma2(racc[5], wp, q2.y);
        fma2(racc[6], wp, q3.x); fma2(racc[7], wp, q3.y);
    }

    float bdv = __ldg(&bd[co]), brv = __ldg(&br[co]);
    #pragma unroll
    for (int p = 0; p < 8; p++) {
        float2 a  = unpack2(acc[p]);
        float2 rr = unpack2(racc[p]);
        float v0 = a.x + bdv; v0 = (v0 >= 0.f) ? v0 : 0.01f*v0;
        float v1 = a.y + bdv; v1 = (v1 >= 0.f) ? v1 : 0.01f*v1;
        float2 o2 = make_float2(v0 + rr.x + brv, v1 + rr.y + brv);
        *reinterpret_cast<float2*>(&out[co*THW_ + sbase + sg*16 + 2*p]) = o2;
    }
}

// ---------------- launch ----------------
extern "C" void kernel_launch(void* const* d_in, const int* in_sizes, int n_in,
                              void* d_out, int out_size)
{
    const float* x     = (const float*)d_in[0];
    const float* W1    = (const float*)d_in[1];
    const float* b1    = (const float*)d_in[2];
    const float* W_off = (const float*)d_in[3];
    const float* b_off = (const float*)d_in[4];
    const float* Wd    = (const float*)d_in[5];
    const float* bd    = (const float*)d_in[6];
    const float* Wr    = (const float*)d_in[7];
    const float* br    = (const float*)d_in[8];
    float* out = (float*)d_out;
    (void)in_sizes; (void)n_in; (void)out_size;

    dim3 cgrid(8, 8, 8);  // (w-tiles, h-tiles, t)

    prep_weights<<<1312, 256>>>(W1, W_off, Wd, Wr);
    // y1 = lrelu(conv3d(x, W1, b1, pad=1))      -> g_y1
    conv3x3x3<64, true,  false, false><<<cgrid, 256>>>(x, b1);
    // offsets = conv3d(y1, W_off, b_off, pad=1) -> g_off
    conv3x3x3<54, false, true,  true ><<<cgrid, 256>>>(nullptr, b_off);
    // out = lrelu(deform(y1, offsets) + bd) + (Wr*x + br)
    deform_fused<<<dim3(64, 8), 256>>>(x, bd, br, out);
}

// round 3
// speedup vs baseline: 1.3048x; 1.1418x over previous
#include <cuda_runtime.h>

#define T_ 8
#define H_ 64
#define W_ 64
#define C_ 64
#define HW_ (H_*W_)
#define THW_ (T_*HW_)

typedef unsigned long long u64;

// ---------------- packed fp32x2 helpers (Blackwell FFMA2) ----------------
__device__ __forceinline__ void fma2(u64& acc, u64 a, u64 b){
    asm("fma.rn.f32x2 %0, %1, %2, %0;" : "+l"(acc) : "l"(a), "l"(b));
}
__device__ __forceinline__ u64 pack2(float x, float y){
    u64 r; asm("mov.b64 %0, {%1, %2};" : "=l"(r) : "f"(x), "f"(y)); return r;
}
__device__ __forceinline__ float2 unpack2(u64 v){
    float2 r; asm("mov.b64 {%0, %1}, %2;" : "=f"(r.x), "=f"(r.y) : "l"(v)); return r;
}

// ---------------- device scratch (allocation-free rule) ----------------
__device__ float g_y1[C_*THW_];         // lrelu(conv1) output
__device__ float g_off[54*THW_];        // offset conv output
__device__ float g_w1t[64*27*64];       // W1    -> [ci][j][co]
__device__ float g_wofft[64*27*64];     // W_off -> [ci][j][co], co padded 54->64 w/ zeros
__device__ float g_wdt[27*64*64];       // Wd    -> [k][c][o]
__device__ float g_wrt[64*64];          // Wr    -> [c][o]

// ---------------- weight reorder (coalesced staging layouts) ----------------
__global__ void prep_weights(const float* __restrict__ W1, const float* __restrict__ Woff,
                             const float* __restrict__ Wd, const float* __restrict__ Wr)
{
    int i = blockIdx.x*256 + threadIdx.x;
    if (i < 110592) {
        int ci = i/(27*64); int r = i%(27*64); int j = r/64; int co = r%64;
        g_w1t[i] = W1[co*1728 + ci*27 + j];
    } else if (i < 221184) {
        int e = i-110592; int ci = e/(27*64); int r = e%(27*64); int j = r/64; int co = r%64;
        g_wofft[e] = (co < 54) ? Woff[co*1728 + ci*27 + j] : 0.f;
    } else if (i < 331776) {
        int e = i-221184; int k = e/4096; int r = e%4096; int c = r/64; int o = r%64;
        g_wdt[e] = Wd[(o*64+c)*27 + k];
    } else if (i < 335872) {
        int e = i-331776; int c = e/64; int o = e%64;
        g_wrt[e] = Wr[o*64 + c];
    }
}

// ---------------- 3x3x3 conv, Cin=64, pad=1, double-buffered pipeline ----------------
// block: (t, 8h x 8w tile); 256 threads = 32 cout-pairs x 8 rows.
template<int COUT, bool LRELU, bool FROM_Y1, bool TO_OFF>
__global__ __launch_bounds__(256)
void conv3x3x3(const float* __restrict__ xin, const float* __restrict__ b)
{
    __shared__ u64 xs2[2][3][10][10];   // dup-packed (v,v) input patch
    __shared__ u64 ws2[2][27][32];      // (w[2cp], w[2cp+1]) per tap

    const float* x  = FROM_Y1 ? g_y1 : xin;
    const float* wt = TO_OFF ? g_wofft : g_w1t;
    float* y        = TO_OFF ? g_off : g_y1;

    int t  = blockIdx.z;
    int h0 = blockIdx.y * 8;
    int w0 = blockIdx.x * 8;
    int tid = threadIdx.x;
    int cp = tid & 31;        // cout pair
    int sg = tid >> 5;        // output row 0..7

    u64 acc[8];
    #pragma unroll
    for (int i = 0; i < 8; i++) acc[i] = 0ull;

    auto stage = [&](int ci, int buf) {
        for (int i = tid; i < 300; i += 256) {
            int dt = i / 100, rem = i % 100;
            int r = rem / 10, c = rem % 10;
            int tt = t + dt - 1, hh = h0 + r - 1, ww = w0 + c - 1;
            float v = 0.f;
            if (tt >= 0 && tt < T_ && hh >= 0 && hh < H_ && ww >= 0 && ww < W_)
                v = __ldg(&x[ci*THW_ + tt*HW_ + hh*W_ + ww]);
            xs2[buf][dt][r][c] = pack2(v, v);
        }
        for (int e = tid; e < 864; e += 256) {
            int j = e >> 5, q = e & 31;
            float2 wv = *reinterpret_cast<const float2*>(&wt[ci*1728 + j*64 + 2*q]);
            ws2[buf][j][q] = pack2(wv.x, wv.y);
        }
    };

    stage(0, 0);
    __syncthreads();

    for (int ci = 0; ci < C_; ci++) {
        int cur = ci & 1;
        if (ci < C_-1) stage(ci+1, cur ^ 1);   // prefetch next cin (overlaps with FMA below)

        #pragma unroll
        for (int kt = 0; kt < 3; kt++) {
            #pragma unroll
            for (int kh = 0; kh < 3; kh++) {
                const ulonglong2* xp =
                    reinterpret_cast<const ulonglong2*>(&xs2[cur][kt][sg + kh][0]);
                ulonglong2 v0 = xp[0], v1 = xp[1], v2 = xp[2], v3 = xp[3], v4 = xp[4];
                u64 xr[10] = {v0.x,v0.y,v1.x,v1.y,v2.x,v2.y,v3.x,v3.y,v4.x,v4.y};
                int j0 = (kt*3 + kh)*3;
                u64 wa = ws2[cur][j0+0][cp], wb = ws2[cur][j0+1][cp], wc = ws2[cur][j0+2][cp];
                #pragma unroll
                for (int w = 0; w < 8; w++) {
                    fma2(acc[w], wa, xr[w]);
                    fma2(acc[w], wb, xr[w+1]);
                    fma2(acc[w], wc, xr[w+2]);
                }
            }
        }
        __syncthreads();
    }

    int co0 = 2*cp, co1 = 2*cp + 1;
    float b0 = (co0 < COUT) ? __ldg(&b[co0]) : 0.f;
    float b1 = (co1 < COUT) ? __ldg(&b[co1]) : 0.f;
    float out0[8], out1[8];
    #pragma unroll
    for (int w = 0; w < 8; w++) {
        float2 v = unpack2(acc[w]);
        float a0 = v.x + b0, a1 = v.y + b1;
        if (LRELU) { a0 = (a0 >= 0.f) ? a0 : 0.01f*a0;
                     a1 = (a1 >= 0.f) ? a1 : 0.01f*a1; }
        out0[w] = a0; out1[w] = a1;
    }
    int base = t*HW_ + (h0 + sg)*W_ + w0;
    if (co0 < COUT) {
        float4* p = reinterpret_cast<float4*>(&y[co0*THW_ + base]);
        p[0] = make_float4(out0[0], out0[1], out0[2], out0[3]);
        p[1] = make_float4(out0[4], out0[5], out0[6], out0[7]);
    }
    if (co1 < COUT) {
        float4* p = reinterpret_cast<float4*>(&y[co1*THW_ + base]);
        p[0] = make_float4(out1[0], out1[1], out1[2], out1[3]);
        p[1] = make_float4(out1[4], out1[5], out1[6], out1[7]);
    }
}

// ---------------- deformable conv + LReLU + fused residual ----------------
// block: 2 rows x 64 w (128 sp) at one t. 256 threads.
// GEMM mapping: 32 cout-pairs x 8 sp-groups(16 sp). Gather mapping: sp = tid&127 fixed.
// Pipelined: gather(k+1)+weights(k+1) issued before GEMM(k); one sync per tap.
__global__ __launch_bounds__(256, 2)
void deform_fused(const float* __restrict__ x, const float* __restrict__ bd,
                  const float* __restrict__ br, float* __restrict__ out)
{
    extern __shared__ float sm[];
    float* cols = sm;            // [2][64*128]
    float* wds  = sm + 16384;    // [2][4096]

    int hp = blockIdx.x;          // row pair 0..31
    int t  = blockIdx.y;
    int tid = threadIdx.x;
    int cp = tid & 31, spg = tid >> 5;      // GEMM roles
    int sp = tid & 127, chalf = tid >> 7;   // gather roles
    int row = sp >> 6, wpos = sp & 63;
    int h = hp*2 + row;
    int obase = t*HW_ + h*W_ + wpos;

    const float* __restrict__ y1 = g_y1;
    const float* __restrict__ offp = g_off;

    u64 acc0[8], acc1[8];
    #pragma unroll
    for (int i = 0; i < 8; i++) { acc0[i] = 0ull; acc1[i] = 0ull; }

    auto stage_w = [&](int k, float* wbuf) {
        #pragma unroll
        for (int r = 0; r < 16; r++)
            wbuf[r*256 + tid] = g_wdt[k*4096 + r*256 + tid];
    };

    auto gather = [&](int k, float* cbuf) {
        int kt = k/9, khh = (k/3)%3, kww = k%3;
        float dh = __ldg(&offp[(2*k + 0)*THW_ + obase]);
        float dw = __ldg(&offp[(2*k + 1)*THW_ + obase]);
        int t_in = t - 1 + kt;
        bool t_ok = (t_in >= 0) && (t_in < T_);
        int t_c = min(max(t_in, 0), T_-1);
        float h_s = (float)(h - 1 + khh) + dh;
        float w_s = (float)(wpos - 1 + kww) + dw;
        float h0f = floorf(h_s), w0f = floorf(w_s);
        float fh = h_s - h0f, fw = w_s - w0f;
        int ih0 = (int)h0f, iw0 = (int)w0f, ih1 = ih0+1, iw1 = iw0+1;
        bool okh0 = (ih0 >= 0) && (ih0 < H_), okh1 = (ih1 >= 0) && (ih1 < H_);
        bool okw0 = (iw0 >= 0) && (iw0 < W_), okw1 = (iw1 >= 0) && (iw1 < W_);
        int ih0c = min(max(ih0,0),H_-1), ih1c = min(max(ih1,0),H_-1);
        int iw0c = min(max(iw0,0),W_-1), iw1c = min(max(iw1,0),W_-1);
        int tb = t_c*HW_;
        int i00 = tb + ih0c*W_ + iw0c, i01 = tb + ih0c*W_ + iw1c;
        int i10 = tb + ih1c*W_ + iw0c, i11 = tb + ih1c*W_ + iw1c;
        float wh0 = 1.f - fh, wh1 = fh, wv0 = 1.f - fw, wv1 = fw;
        float q00 = (t_ok && okh0 && okw0) ? wh0*wv0 : 0.f;
        float q01 = (t_ok && okh0 && okw1) ? wh0*wv1 : 0.f;
        float q10 = (t_ok && okh1 && okw0) ? wh1*wv0 : 0.f;
        float q11 = (t_ok && okh1 && okw1) ? wh1*wv1 : 0.f;
        #pragma unroll 4
        for (int r = 0; r < 32; r++) {
            int c = 2*r + chalf;
            const float* p = y1 + c*THW_;
            float v = fmaf(q00, __ldg(p+i00),
                      fmaf(q01, __ldg(p+i01),
                      fmaf(q10, __ldg(p+i10), q11*__ldg(p+i11))));
            cbuf[c*128 + sp] = v;
        }
    };

    auto gemm = [&](const float* cbuf, const float* wbuf) {
        #pragma unroll 8
        for (int c = 0; c < 64; c++) {
            float2 wv = *reinterpret_cast<const float2*>(&wbuf[c*64 + 2*cp]);
            u64 wp0 = pack2(wv.x, wv.x), wp1 = pack2(wv.y, wv.y);
            const ulonglong2* cp2 =
                reinterpret_cast<const ulonglong2*>(&cbuf[c*128 + spg*16]);
            ulonglong2 q0 = cp2[0], q1 = cp2[1], q2 = cp2[2], q3 = cp2[3];
            fma2(acc0[0], wp0, q0.x); fma2(acc1[0], wp1, q0.x);
            fma2(acc0[1], wp0, q0.y); fma2(acc1[1], wp1, q0.y);
            fma2(acc0[2], wp0, q1.x); fma2(acc1[2], wp1, q1.x);
            fma2(acc0[3], wp0, q1.y); fma2(acc1[3], wp1, q1.y);
            fma2(acc0[4], wp0, q2.x); fma2(acc1[4], wp1, q2.x);
            fma2(acc0[5], wp0, q2.y); fma2(acc1[5], wp1, q2.y);
            fma2(acc0[6], wp0, q3.x); fma2(acc1[6], wp1, q3.x);
            fma2(acc0[7], wp0, q3.y); fma2(acc1[7], wp1, q3.y);
        }
    };

    stage_w(0, wds);
    gather(0, cols);
    __syncthreads();

    for (int k = 0; k < 27; k++) {
        int cur = k & 1;
        if (k < 26) {                       // prefetch next tap (overlaps with GEMM)
            stage_w(k+1, wds + (cur^1)*4096);
            gather(k+1, cols + (cur^1)*8192);
        }
        gemm(cols + cur*8192, wds + cur*4096);
        __syncthreads();
    }

    // convert acc: lrelu(acc + bd) + br, then accumulate residual GEMM into it
    int co0 = 2*cp, co1 = co0 + 1;
    {
        float bd0 = __ldg(&bd[co0]), bd1 = __ldg(&bd[co1]);
        float br0 = __ldg(&br[co0]), br1 = __ldg(&br[co1]);
        #pragma unroll
        for (int p = 0; p < 8; p++) {
            float2 a = unpack2(acc0[p]);
            float v0 = a.x + bd0; v0 = (v0 >= 0.f) ? v0 : 0.01f*v0;
            float v1 = a.y + bd0; v1 = (v1 >= 0.f) ? v1 : 0.01f*v1;
            acc0[p] = pack2(v0 + br0, v1 + br0);
            float2 c2 = unpack2(acc1[p]);
            float u0 = c2.x + bd1; u0 = (u0 >= 0.f) ? u0 : 0.01f*u0;
            float u1 = c2.y + bd1; u1 = (u1 >= 0.f) ? u1 : 0.01f*u1;
            acc1[p] = pack2(u0 + br1, u1 + br1);
        }
    }

    // residual 1x1: stage x tile + Wr, one more GEMM step
    #pragma unroll 4
    for (int r = 0; r < 32; r++) {
        int c = 2*r + chalf;
        cols[c*128 + sp] = __ldg(&x[c*THW_ + obase]);
    }
    #pragma unroll
    for (int r = 0; r < 16; r++)
        wds[r*256 + tid] = g_wrt[r*256 + tid];
    __syncthreads();
    gemm(cols, wds);

    // write out
    int rowp = spg >> 2;
    int wq = (spg & 3) * 16;
    int gbase = t*HW_ + (hp*2 + rowp)*W_ + wq;
    #pragma unroll
    for (int p = 0; p < 8; p++) {
        float2 a = unpack2(acc0[p]);
        *reinterpret_cast<float2*>(&out[co0*THW_ + gbase + 2*p]) = a;
        float2 c2 = unpack2(acc1[p]);
        *reinterpret_cast<float2*>(&out[co1*THW_ + gbase + 2*p]) = c2;
    }
}

// ---------------- launch ----------------
extern "C" void kernel_launch(void* const* d_in, const int* in_sizes, int n_in,
                              void* d_out, int out_size)
{
    const float* x     = (const float*)d_in[0];
    const float* W1    = (const float*)d_in[1];
    const float* b1    = (const float*)d_in[2];
    const float* W_off = (const float*)d_in[3];
    const float* b_off = (const float*)d_in[4];
    const float* Wd    = (const float*)d_in[5];
    const float* bd    = (const float*)d_in[6];
    const float* Wr    = (const float*)d_in[7];
    const float* br    = (const float*)d_in[8];
    float* out = (float*)d_out;
    (void)in_sizes; (void)n_in; (void)out_size;

    static int smem_set = 0;
    const int DSMEM = (16384*2 + 4096*2) * 4;   // 98304 B
    cudaFuncSetAttribute(deform_fused, cudaFuncAttributeMaxDynamicSharedMemorySize, DSMEM);
    (void)smem_set;

    dim3 cgrid(8, 8, 8);  // (w-tiles, h-tiles, t)

    prep_weights<<<1312, 256>>>(W1, W_off, Wd, Wr);
    // y1 = lrelu(conv3d(x, W1, b1, pad=1))      -> g_y1
    conv3x3x3<64, true,  false, false><<<cgrid, 256>>>(x, b1);
    // offsets = conv3d(y1, W_off, b_off, pad=1) -> g_off
    conv3x3x3<54, false, true,  true ><<<cgrid, 256>>>(nullptr, b_off);
    // out = lrelu(deform(y1, offsets) + bd) + (Wr*x + br)
    deform_fused<<<dim3(32, 8), 256, DSMEM>>>(x, bd, br, out);
}

// round 7
// speedup vs baseline: 1.5382x; 1.1788x over previous
#include <cuda_runtime.h>

#define T_ 8
#define H_ 64
#define W_ 64
#define C_ 64
#define HW_ (H_*W_)
#define THW_ (T_*HW_)

typedef unsigned long long u64;

// ---------------- packed fp32x2 helpers (Blackwell FFMA2) ----------------
__device__ __forceinline__ void fma2(u64& acc, u64 a, u64 b){
    asm("fma.rn.f32x2 %0, %1, %2, %0;" : "+l"(acc) : "l"(a), "l"(b));
}
__device__ __forceinline__ u64 pack2(float x, float y){
    u64 r; asm("mov.b64 %0, {%1, %2};" : "=l"(r) : "f"(x), "f"(y)); return r;
}
__device__ __forceinline__ float2 unpack2(u64 v){
    float2 r; asm("mov.b64 {%0, %1}, %2;" : "=f"(r.x), "=f"(r.y) : "l"(v)); return r;
}

// ---------------- device scratch (allocation-free rule) ----------------
__device__ float g_y1[C_*THW_];         // lrelu(conv1) output
__device__ float g_off[54*THW_];        // offset conv output
__device__ float g_w1t[64*27*64];       // W1    -> [ci][j][co]
__device__ float g_wofft[64*27*64];     // W_off -> [ci][j][co], co padded 54->64 w/ zeros
__device__ float g_wdt[27*64*64];       // Wd    -> [k][c][o]
__device__ float g_wrt[64*64];          // Wr    -> [c][o]

// ---------------- weight reorder (coalesced staging layouts) ----------------
__global__ void prep_weights(const float* __restrict__ W1, const float* __restrict__ Woff,
                             const float* __restrict__ Wd, const float* __restrict__ Wr)
{
    int i = blockIdx.x*256 + threadIdx.x;
    if (i < 110592) {
        int ci = i/(27*64); int r = i%(27*64); int j = r/64; int co = r%64;
        g_w1t[i] = W1[co*1728 + ci*27 + j];
    } else if (i < 221184) {
        int e = i-110592; int ci = e/(27*64); int r = e%(27*64); int j = r/64; int co = r%64;
        g_wofft[e] = (co < 54) ? Woff[co*1728 + ci*27 + j] : 0.f;
    } else if (i < 331776) {
        int e = i-221184; int k = e/4096; int r = e%4096; int c = r/64; int o = r%64;
        g_wdt[e] = Wd[(o*64+c)*27 + k];
    } else if (i < 335872) {
        int e = i-331776; int c = e/64; int o = e%64;
        g_wrt[e] = Wr[o*64 + c];
    }
}

// ---------------- 3x3x3 conv, Cin=64, pad=1, reg-pipelined staging ----------------
// block: (t, 8h x 8w tile); 256 threads = 32 cout-pairs x 8 rows.
template<int COUT, bool LRELU, bool FROM_Y1, bool TO_OFF>
__global__ __launch_bounds__(256)
void conv3x3x3(const float* __restrict__ xin, const float* __restrict__ b)
{
    __shared__ u64 xs2[2][300];   // dup-packed (v,v) input patch (3x10x10 flat)
    __shared__ u64 ws2[2][864];   // (w[2cp], w[2cp+1]) per tap (27x32 flat)

    const float* x  = FROM_Y1 ? g_y1 : xin;
    const float* wt = TO_OFF ? g_wofft : g_w1t;
    float* y        = TO_OFF ? g_off : g_y1;

    int t  = blockIdx.z;
    int h0 = blockIdx.y * 8;
    int w0 = blockIdx.x * 8;
    int tid = threadIdx.x;
    int cp = tid & 31;        // cout pair
    int sg = tid >> 5;        // output row 0..7

    // --- per-thread staging descriptors (fixed across cin) ---
    int xoff0 = 0, xoff1 = 0; bool xval0, xval1 = false;
    {
        int e = tid, dt = e/100, rem = e%100, r = rem/10, c = rem%10;
        int tt = t+dt-1, hh = h0+r-1, ww = w0+c-1;
        xval0 = (tt>=0 && tt<T_ && hh>=0 && hh<H_ && ww>=0 && ww<W_);
        if (xval0) xoff0 = tt*HW_ + hh*W_ + ww;
    }
    bool has1 = (tid < 44);
    if (has1) {
        int e = tid+256, dt = e/100, rem = e%100, r = rem/10, c = rem%10;
        int tt = t+dt-1, hh = h0+r-1, ww = w0+c-1;
        xval1 = (tt>=0 && tt<T_ && hh>=0 && hh<H_ && ww>=0 && ww<W_);
        if (xval1) xoff1 = tt*HW_ + hh*W_ + ww;
    }
    int wb0, wb1, wb2, wb3 = 0;
    {
        int e0 = tid, e1 = tid+256, e2 = tid+512, e3 = tid+768;
        wb0 = (e0>>5)*64 + 2*(e0&31);
        wb1 = (e1>>5)*64 + 2*(e1&31);
        wb2 = (e2>>5)*64 + 2*(e2&31);
        if (tid < 96) wb3 = (e3>>5)*64 + 2*(e3&31);
    }
    bool wact3 = (tid < 96);

    float xv0 = 0.f, xv1 = 0.f;
    float2 wv0, wv1, wv2, wv3;

    auto issue = [&](int ci){
        const float* xp = x + ci*THW_;
        xv0 = xval0 ? __ldg(xp + xoff0) : 0.f;
        if (has1) xv1 = xval1 ? __ldg(xp + xoff1) : 0.f;
        const float* wp = wt + ci*1728;
        wv0 = *reinterpret_cast<const float2*>(wp + wb0);
        wv1 = *reinterpret_cast<const float2*>(wp + wb1);
        wv2 = *reinterpret_cast<const float2*>(wp + wb2);
        if (wact3) wv3 = *reinterpret_cast<const float2*>(wp + wb3);
    };
    auto store = [&](int buf){
        xs2[buf][tid] = pack2(xv0, xv0);
        if (has1) xs2[buf][tid+256] = pack2(xv1, xv1);
        ws2[buf][tid]     = pack2(wv0.x, wv0.y);
        ws2[buf][tid+256] = pack2(wv1.x, wv1.y);
        ws2[buf][tid+512] = pack2(wv2.x, wv2.y);
        if (wact3) ws2[buf][tid+768] = pack2(wv3.x, wv3.y);
    };

    u64 acc[8];
    #pragma unroll
    for (int i = 0; i < 8; i++) acc[i] = 0ull;

    issue(0);

    for (int ci = 0; ci < C_; ci++) {
        int cur = ci & 1;
        store(cur);
        __syncthreads();
        if (ci < C_-1) issue(ci+1);   // LDGs hidden under the FMA loop below

        #pragma unroll
        for (int kt = 0; kt < 3; kt++) {
            #pragma unroll
            for (int kh = 0; kh < 3; kh++) {
                const ulonglong2* xp =
                    reinterpret_cast<const ulonglong2*>(&xs2[cur][kt*100 + (sg+kh)*10]);
                ulonglong2 v0 = xp[0], v1 = xp[1], v2 = xp[2], v3 = xp[3], v4 = xp[4];
                u64 xr[10] = {v0.x,v0.y,v1.x,v1.y,v2.x,v2.y,v3.x,v3.y,v4.x,v4.y};
                int j0 = (kt*3 + kh)*3;
                u64 wa = ws2[cur][(j0+0)*32+cp], wb = ws2[cur][(j0+1)*32+cp],
                    wc = ws2[cur][(j0+2)*32+cp];
                #pragma unroll
                for (int w = 0; w < 8; w++) {
                    fma2(acc[w], wa, xr[w]);
                    fma2(acc[w], wb, xr[w+1]);
                    fma2(acc[w], wc, xr[w+2]);
                }
            }
        }
    }

    int co0 = 2*cp, co1 = 2*cp + 1;
    float b0 = (co0 < COUT) ? __ldg(&b[co0]) : 0.f;
    float b1 = (co1 < COUT) ? __ldg(&b[co1]) : 0.f;
    float out0[8], out1[8];
    #pragma unroll
    for (int w = 0; w < 8; w++) {
        float2 v = unpack2(acc[w]);
        float a0 = v.x + b0, a1 = v.y + b1;
        if (LRELU) { a0 = (a0 >= 0.f) ? a0 : 0.01f*a0;
                     a1 = (a1 >= 0.f) ? a1 : 0.01f*a1; }
        out0[w] = a0; out1[w] = a1;
    }
    int base = t*HW_ + (h0 + sg)*W_ + w0;
    if (co0 < COUT) {
        float4* p = reinterpret_cast<float4*>(&y[co0*THW_ + base]);
        p[0] = make_float4(out0[0], out0[1], out0[2], out0[3]);
        p[1] = make_float4(out0[4], out0[5], out0[6], out0[7]);
    }
    if (co1 < COUT) {
        float4* p = reinterpret_cast<float4*>(&y[co1*THW_ + base]);
        p[0] = make_float4(out1[0], out1[1], out1[2], out1[3]);
        p[1] = make_float4(out1[4], out1[5], out1[6], out1[7]);
    }
}

// ---------------- deformable conv + LReLU + fused residual ----------------
// block: 2 rows x 64 w (128 sp) at one t. 256 threads.
// GEMM: 32 cout-pairs x 8 sp-groups(16 sp), acc 2co x 16sp.
// Per tap: issue(j+2)->regs / gemm(j) / combine(j) chunk pipeline; one sync per tap.
__global__ __launch_bounds__(256, 2)
void deform_fused(const float* __restrict__ x, const float* __restrict__ bd,
                  const float* __restrict__ br, float* __restrict__ out)
{
    extern __shared__ float sm[];
    float* cols = sm;            // [2][64*128]
    float* wds  = sm + 16384;    // [2][4096]

    int hp = blockIdx.x;          // row pair 0..31
    int t  = blockIdx.y;
    int tid = threadIdx.x;
    int cp = tid & 31, spg = tid >> 5;      // GEMM roles
    int sp = tid & 127, chalf = tid >> 7;   // gather roles
    int row = sp >> 6, wpos = sp & 63;
    int h = hp*2 + row;
    int obase = t*HW_ + h*W_ + wpos;

    const float* __restrict__ y1 = g_y1;
    const float* __restrict__ offp = g_off;

    u64 acc0[8], acc1[8];
    #pragma unroll
    for (int i = 0; i < 8; i++) { acc0[i] = 0ull; acc1[i] = 0ull; }

    int gi0, gi1, gi2, gi3;
    float gq0, gq1, gq2, gq3;

    auto compute_idx = [&](int kk, float dh, float dw){
        int kt = kk/9, khh = (kk/3)%3, kww = kk%3;
        int t_in = t - 1 + kt;
        bool t_ok = (t_in >= 0) && (t_in < T_);
        int t_c = min(max(t_in, 0), T_-1);
        float h_s = (float)(h - 1 + khh) + dh;
        float w_s = (float)(wpos - 1 + kww) + dw;
        float h0f = floorf(h_s), w0f = floorf(w_s);
        float fh = h_s - h0f, fw = w_s - w0f;
        int ih0 = (int)h0f, iw0 = (int)w0f, ih1 = ih0+1, iw1 = iw0+1;
        bool okh0 = (ih0 >= 0) && (ih0 < H_), okh1 = (ih1 >= 0) && (ih1 < H_);
        bool okw0 = (iw0 >= 0) && (iw0 < W_), okw1 = (iw1 >= 0) && (iw1 < W_);
        int ih0c = min(max(ih0,0),H_-1), ih1c = min(max(ih1,0),H_-1);
        int iw0c = min(max(iw0,0),W_-1), iw1c = min(max(iw1,0),W_-1);
        int tb = t_c*HW_;
        gi0 = tb + ih0c*W_ + iw0c; gi1 = tb + ih0c*W_ + iw1c;
        gi2 = tb + ih1c*W_ + iw0c; gi3 = tb + ih1c*W_ + iw1c;
        float wh0 = 1.f - fh, wh1 = fh, wv0 = 1.f - fw, wv1 = fw;
        gq0 = (t_ok && okh0 && okw0) ? wh0*wv0 : 0.f;
        gq1 = (t_ok && okh0 && okw1) ? wh0*wv1 : 0.f;
        gq2 = (t_ok && okh1 && okw0) ? wh1*wv0 : 0.f;
        gq3 = (t_ok && okh1 && okw1) ? wh1*wv1 : 0.f;
    };

    auto gemm_range = [&](const float* cbuf, const float* wbuf, int c0, int c1){
        #pragma unroll
        for (int c = c0; c < c1; c++) {
            float2 wv = *reinterpret_cast<const float2*>(&wbuf[c*64 + 2*cp]);
            u64 wp0 = pack2(wv.x, wv.x), wp1 = pack2(wv.y, wv.y);
            const ulonglong2* cp2 =
                reinterpret_cast<const ulonglong2*>(&cbuf[c*128 + spg*16]);
            ulonglong2 q0 = cp2[0], q1 = cp2[1], q2 = cp2[2], q3 = cp2[3];
            fma2(acc0[0], wp0, q0.x); fma2(acc1[0], wp1, q0.x);
            fma2(acc0[1], wp0, q0.y); fma2(acc1[1], wp1, q0.y);
            fma2(acc0[2], wp0, q1.x); fma2(acc1[2], wp1, q1.x);
            fma2(acc0[3], wp0, q1.y); fma2(acc1[3], wp1, q1.y);
            fma2(acc0[4], wp0, q2.x); fma2(acc1[4], wp1, q2.x);
            fma2(acc0[5], wp0, q2.y); fma2(acc1[5], wp1, q2.y);
            fma2(acc0[6], wp0, q3.x); fma2(acc1[6], wp1, q3.x);
            fma2(acc0[7], wp0, q3.y); fma2(acc1[7], wp1, q3.y);
        }
    };

    // ---- prologue: tap 0 gathered inline; weights 0 staged ----
    {
        float dh = __ldg(&offp[0*THW_ + obase]);
        float dw = __ldg(&offp[1*THW_ + obase]);
        compute_idx(0, dh, dw);
        #pragma unroll 4
        for (int r = 0; r < 32; r++) {
            int c = 2*r + chalf;
            const float* p = y1 + c*THW_;
            float v = fmaf(gq0, __ldg(p+gi0),
                      fmaf(gq1, __ldg(p+gi1),
                      fmaf(gq2, __ldg(p+gi2), gq3*__ldg(p+gi3))));
            cols[c*128 + sp] = v;
        }
        const float4* p4 = reinterpret_cast<const float4*>(g_wdt + tid*16);
        float4 a = p4[0], bq = p4[1], cq = p4[2], dq = p4[3];
        float4* q4 = reinterpret_cast<float4*>(wds + tid*16);
        q4[0] = a; q4[1] = bq; q4[2] = cq; q4[3] = dq;
    }
    float dh_n = __ldg(&offp[2*THW_ + obase]);   // offsets for tap 1
    float dw_n = __ldg(&offp[3*THW_ + obase]);

    float vb0[16], vb1[16];
    float4 wr0, wr1, wr2, wr3;

    for (int k = 0; k < 27; k++) {
        int cur = k & 1;
        const float* ccur = cols + cur*8192;
        float*       cnxt = cols + (cur^1)*8192;
        const float* wcur = wds + cur*4096;
        float*       wnxt = wds + (cur^1)*4096;
        __syncthreads();

        float dh_nn = 0.f, dw_nn = 0.f;
        if (k < 25) {
            dh_nn = __ldg(&offp[(2*k+4)*THW_ + obase]);
            dw_nn = __ldg(&offp[(2*k+5)*THW_ + obase]);
        }

        if (k < 26) {
            compute_idx(k+1, dh_n, dw_n);
            // issue next-tap weights into regs
            const float4* p4 = reinterpret_cast<const float4*>(g_wdt + (k+1)*4096 + tid*16);
            wr0 = p4[0]; wr1 = p4[1]; wr2 = p4[2]; wr3 = p4[3];

            // chunk pipeline: issue(j+2) / gemm(j) / combine(j)
            #pragma unroll
            for (int q = 0; q < 4; q++) {
                int c = 2*q + chalf;
                const float* p = y1 + c*THW_;
                vb0[4*q+0]=__ldg(p+gi0); vb0[4*q+1]=__ldg(p+gi1);
                vb0[4*q+2]=__ldg(p+gi2); vb0[4*q+3]=__ldg(p+gi3);
            }
            #pragma unroll
            for (int q = 0; q < 4; q++) {
                int c = 2*(4+q) + chalf;
                const float* p = y1 + c*THW_;
                vb1[4*q+0]=__ldg(p+gi0); vb1[4*q+1]=__ldg(p+gi1);
                vb1[4*q+2]=__ldg(p+gi2); vb1[4*q+3]=__ldg(p+gi3);
            }
            #pragma unroll
            for (int j = 0; j < 8; j++) {
                gemm_range(ccur, wcur, j*8, j*8+8);
                float* vb = (j & 1) ? vb1 : vb0;
                #pragma unroll
                for (int q = 0; q < 4; q++) {
                    int c = 2*(4*j+q) + chalf;
                    float v = fmaf(gq0, vb[4*q+0],
                              fmaf(gq1, vb[4*q+1],
                              fmaf(gq2, vb[4*q+2], gq3*vb[4*q+3])));
                    cnxt[c*128 + sp] = v;
                }
                if (j < 6) {
                    #pragma unroll
                    for (int q = 0; q < 4; q++) {
                        int c = 2*(4*(j+2)+q) + chalf;
                        const float* p = y1 + c*THW_;
                        vb[4*q+0]=__ldg(p+gi0); vb[4*q+1]=__ldg(p+gi1);
                        vb[4*q+2]=__ldg(p+gi2); vb[4*q+3]=__ldg(p+gi3);
                    }
                }
            }
            // store next-tap weights
            float4* q4 = reinterpret_cast<float4*>(wnxt + tid*16);
            q4[0] = wr0; q4[1] = wr1; q4[2] = wr2; q4[3] = wr3;
        } else {
            gemm_range(ccur, wcur, 0, 64);
        }
        dh_n = dh_nn; dw_n = dw_nn;
    }

    // convert acc: lrelu(acc + bd) + br
    int co0 = 2*cp, co1 = co0 + 1;
    {
        float bd0 = __ldg(&bd[co0]), bd1 = __ldg(&bd[co1]);
        float br0 = __ldg(&br[co0]), br1 = __ldg(&br[co1]);
        #pragma unroll
        for (int p = 0; p < 8; p++) {
            float2 a = unpack2(acc0[p]);
            float v0 = a.x + bd0; v0 = (v0 >= 0.f) ? v0 : 0.01f*v0;
            float v1 = a.y + bd0; v1 = (v1 >= 0.f) ? v1 : 0.01f*v1;
            acc0[p] = pack2(v0 + br0, v1 + br0);
            float2 c2 = unpack2(acc1[p]);
            float u0 = c2.x + bd1; u0 = (u0 >= 0.f) ? u0 : 0.01f*u0;
            float u1 = c2.y + bd1; u1 = (u1 >= 0.f) ? u1 : 0.01f*u1;
            acc1[p] = pack2(u0 + br1, u1 + br1);
        }
    }

    // residual 1x1: stage x tile + Wr, one more GEMM pass
    __syncthreads();
    #pragma unroll 4
    for (int r = 0; r < 32; r++) {
        int c = 2*r + chalf;
        cols[c*128 + sp] = __ldg(&x[c*THW_ + obase]);
    }
    #pragma unroll
    for (int r = 0; r < 16; r++)
        wds[r*256 + tid] = g_wrt[r*256 + tid];
    __syncthreads();
    gemm_range(cols, wds, 0, 64);

    // write out
    int rowp = spg >> 2;
    int wq = (spg & 3) * 16;
    int gbase = t*HW_ + (hp*2 + rowp)*W_ + wq;
    #pragma unroll
    for (int p = 0; p < 8; p++) {
        float2 a = unpack2(acc0[p]);
        *reinterpret_cast<float2*>(&out[co0*THW_ + gbase + 2*p]) = a;
        float2 c2 = unpack2(acc1[p]);
        *reinterpret_cast<float2*>(&out[co1*THW_ + gbase + 2*p]) = c2;
    }
}

// ---------------- launch ----------------
extern "C" void kernel_launch(void* const* d_in, const int* in_sizes, int n_in,
                              void* d_out, int out_size)
{
    const float* x     = (const float*)d_in[0];
    const float* W1    = (const float*)d_in[1];
    const float* b1    = (const float*)d_in[2];
    const float* W_off = (const float*)d_in[3];
    const float* b_off = (const float*)d_in[4];
    const float* Wd    = (const float*)d_in[5];
    const float* bd    = (const float*)d_in[6];
    const float* Wr    = (const float*)d_in[7];
    const float* br    = (const float*)d_in[8];
    float* out = (float*)d_out;
    (void)in_sizes; (void)n_in; (void)out_size;

    const int DSMEM = (16384*2 + 4096*2) * 4;   // 98304 B
    cudaFuncSetAttribute(deform_fused, cudaFuncAttributeMaxDynamicSharedMemorySize, DSMEM);

    dim3 cgrid(8, 8, 8);  // (w-tiles, h-tiles, t)

    prep_weights<<<1312, 256>>>(W1, W_off, Wd, Wr);
    // y1 = lrelu(conv3d(x, W1, b1, pad=1))      -> g_y1
    conv3x3x3<64, true,  false, false><<<cgrid, 256>>>(x, b1);
    // offsets = conv3d(y1, W_off, b_off, pad=1) -> g_off
    conv3x3x3<54, false, true,  true ><<<cgrid, 256>>>(nullptr, b_off);
    // out = lrelu(deform(y1, offsets) + bd) + (Wr*x + br)
    deform_fused<<<dim3(32, 8), 256, DSMEM>>>(x, bd, br, out);
}

// round 8
// speedup vs baseline: 1.5603x; 1.0144x over previous
#include <cuda_runtime.h>

#define T_ 8
#define H_ 64
#define W_ 64
#define C_ 64
#define HW_ (H_*W_)
#define THW_ (T_*HW_)

typedef unsigned long long u64;

// ---------------- packed fp32x2 helpers (Blackwell FFMA2) ----------------
__device__ __forceinline__ void fma2(u64& acc, u64 a, u64 b){
    asm("fma.rn.f32x2 %0, %1, %2, %0;" : "+l"(acc) : "l"(a), "l"(b));
}
__device__ __forceinline__ u64 pack2(float x, float y){
    u64 r; asm("mov.b64 %0, {%1, %2};" : "=l"(r) : "f"(x), "f"(y)); return r;
}
__device__ __forceinline__ float2 unpack2(u64 v){
    float2 r; asm("mov.b64 {%0, %1}, %2;" : "=f"(r.x), "=f"(r.y) : "l"(v)); return r;
}

// ---------------- cp.async helpers (zero-register staging) ----------------
__device__ __forceinline__ void cp16(void* dst, const void* src){
    unsigned d = (unsigned)__cvta_generic_to_shared(dst);
    asm volatile("cp.async.ca.shared.global [%0], [%1], 16;" :: "r"(d), "l"(src));
}
__device__ __forceinline__ void cp4(void* dst, const void* src){
    unsigned d = (unsigned)__cvta_generic_to_shared(dst);
    asm volatile("cp.async.ca.shared.global [%0], [%1], 4;" :: "r"(d), "l"(src));
}
__device__ __forceinline__ void cp_commit(){ asm volatile("cp.async.commit_group;"); }
__device__ __forceinline__ void cp_wait0(){ asm volatile("cp.async.wait_group 0;"); }

// ---------------- device scratch (allocation-free rule) ----------------
__device__ float g_y1[C_*THW_];         // lrelu(conv1) output
__device__ float g_off[54*THW_];        // offset conv output
__device__ float g_w1t[64*27*64];       // W1    -> [ci][j][co]
__device__ float g_wofft[64*27*64];     // W_off -> [ci][j][co], co padded 54->64 w/ zeros
__device__ float g_wdt[27*64*64];       // Wd    -> [k][c][o]
__device__ float g_wrt[64*64];          // Wr    -> [c][o]

// ---------------- weight reorder (coalesced staging layouts) ----------------
__global__ void prep_weights(const float* __restrict__ W1, const float* __restrict__ Woff,
                             const float* __restrict__ Wd, const float* __restrict__ Wr)
{
    int i = blockIdx.x*256 + threadIdx.x;
    if (i < 110592) {
        int ci = i/(27*64); int r = i%(27*64); int j = r/64; int co = r%64;
        g_w1t[i] = W1[co*1728 + ci*27 + j];
    } else if (i < 221184) {
        int e = i-110592; int ci = e/(27*64); int r = e%(27*64); int j = r/64; int co = r%64;
        g_wofft[e] = (co < 54) ? Woff[co*1728 + ci*27 + j] : 0.f;
    } else if (i < 331776) {
        int e = i-221184; int k = e/4096; int r = e%4096; int c = r/64; int o = r%64;
        g_wdt[e] = Wd[(o*64+c)*27 + k];
    } else if (i < 335872) {
        int e = i-331776; int c = e/64; int o = e%64;
        g_wrt[e] = Wr[o*64 + c];
    }
}

// ---------------- 3x3x3 conv, Cin=64, pad=1, cp.async weights + reg-staged x ----------
// block: (t, 8h x 8w tile); 256 threads = 32 cout-pairs x 8 rows.
template<int COUT, bool LRELU, bool FROM_Y1, bool TO_OFF>
__global__ __launch_bounds__(256, 3)
void conv3x3x3(const float* __restrict__ xin, const float* __restrict__ b)
{
    __shared__ u64 xs2[2][300];   // dup-packed (v,v) input patch (3x10x10 flat)
    __shared__ u64 ws2[2][864];   // == contiguous 1728 floats of wt[ci] (pair layout)

    const float* x  = FROM_Y1 ? g_y1 : xin;
    const float* wt = TO_OFF ? g_wofft : g_w1t;
    float* y        = TO_OFF ? g_off : g_y1;

    int t  = blockIdx.z;
    int h0 = blockIdx.y * 8;
    int w0 = blockIdx.x * 8;
    int tid = threadIdx.x;
    int cp = tid & 31;        // cout pair
    int sg = tid >> 5;        // output row 0..7

    // --- per-thread x staging descriptors (fixed across cin) ---
    int xoff0 = 0, xoff1 = 0; bool xval0, xval1 = false;
    {
        int e = tid, dt = e/100, rem = e%100, r = rem/10, c = rem%10;
        int tt = t+dt-1, hh = h0+r-1, ww = w0+c-1;
        xval0 = (tt>=0 && tt<T_ && hh>=0 && hh<H_ && ww>=0 && ww<W_);
        if (xval0) xoff0 = tt*HW_ + hh*W_ + ww;
    }
    bool has1 = (tid < 44);
    if (has1) {
        int e = tid+256, dt = e/100, rem = e%100, r = rem/10, c = rem%10;
        int tt = t+dt-1, hh = h0+r-1, ww = w0+c-1;
        xval1 = (tt>=0 && tt<T_ && hh>=0 && hh<H_ && ww>=0 && ww<W_);
        if (xval1) xoff1 = tt*HW_ + hh*W_ + ww;
    }

    float xv0 = 0.f, xv1 = 0.f;

    auto issue_x = [&](int ci){
        const float* xp = x + ci*THW_;
        xv0 = xval0 ? __ldg(xp + xoff0) : 0.f;
        if (has1) xv1 = xval1 ? __ldg(xp + xoff1) : 0.f;
    };
    auto store_x = [&](int buf){
        xs2[buf][tid] = pack2(xv0, xv0);
        if (has1) xs2[buf][tid+256] = pack2(xv1, xv1);
    };
    auto cp_w = [&](int ci, int buf){
        float* dst = reinterpret_cast<float*>(ws2[buf]);
        const float* src = wt + ci*1728;
        cp16(dst + 4*tid, src + 4*tid);
        if (tid < 176) cp16(dst + 4*(256+tid), src + 4*(256+tid));
        cp_commit();
    };

    u64 acc[8];
    #pragma unroll
    for (int i = 0; i < 8; i++) acc[i] = 0ull;

    // prologue: stage cin 0
    issue_x(0);
    cp_w(0, 0);
    store_x(0);
    cp_wait0();
    __syncthreads();

    for (int ci = 0; ci < C_; ci++) {
        int cur = ci & 1;
        if (ci < C_-1) { issue_x(ci+1); cp_w(ci+1, cur^1); }

        #pragma unroll
        for (int kt = 0; kt < 3; kt++) {
            #pragma unroll
            for (int kh = 0; kh < 3; kh++) {
                const ulonglong2* xp =
                    reinterpret_cast<const ulonglong2*>(&xs2[cur][kt*100 + (sg+kh)*10]);
                ulonglong2 v0 = xp[0], v1 = xp[1], v2 = xp[2], v3 = xp[3], v4 = xp[4];
                u64 xr[10] = {v0.x,v0.y,v1.x,v1.y,v2.x,v2.y,v3.x,v3.y,v4.x,v4.y};
                int j0 = (kt*3 + kh)*3;
                u64 wa = ws2[cur][(j0+0)*32+cp], wb = ws2[cur][(j0+1)*32+cp],
                    wc = ws2[cur][(j0+2)*32+cp];
                #pragma unroll
                for (int w = 0; w < 8; w++) {
                    fma2(acc[w], wa, xr[w]);
                    fma2(acc[w], wb, xr[w+1]);
                    fma2(acc[w], wc, xr[w+2]);
                }
            }
        }
        if (ci < C_-1) { store_x(cur^1); cp_wait0(); }
        __syncthreads();
    }

    int co0 = 2*cp, co1 = 2*cp + 1;
    float b0 = (co0 < COUT) ? __ldg(&b[co0]) : 0.f;
    float b1 = (co1 < COUT) ? __ldg(&b[co1]) : 0.f;
    float out0[8], out1[8];
    #pragma unroll
    for (int w = 0; w < 8; w++) {
        float2 v = unpack2(acc[w]);
        float a0 = v.x + b0, a1 = v.y + b1;
        if (LRELU) { a0 = (a0 >= 0.f) ? a0 : 0.01f*a0;
                     a1 = (a1 >= 0.f) ? a1 : 0.01f*a1; }
        out0[w] = a0; out1[w] = a1;
    }
    int base = t*HW_ + (h0 + sg)*W_ + w0;
    if (co0 < COUT) {
        float4* p = reinterpret_cast<float4*>(&y[co0*THW_ + base]);
        p[0] = make_float4(out0[0], out0[1], out0[2], out0[3]);
        p[1] = make_float4(out0[4], out0[5], out0[6], out0[7]);
    }
    if (co1 < COUT) {
        float4* p = reinterpret_cast<float4*>(&y[co1*THW_ + base]);
        p[0] = make_float4(out1[0], out1[1], out1[2], out1[3]);
        p[1] = make_float4(out1[4], out1[5], out1[6], out1[7]);
    }
}

// ---------------- deformable conv + LReLU + fused residual ----------------
// block: 2 rows x 64 w (128 sp) at one t. 256 threads.
// GEMM: 32 cout-pairs x 8 sp-groups(16 sp), acc 2co x 16sp.
// Weights via cp.async (no regs); gather distance-1 reg pipeline (16-float buffer).
__global__ __launch_bounds__(256, 2)
void deform_fused(const float* __restrict__ x, const float* __restrict__ bd,
                  const float* __restrict__ br, float* __restrict__ out)
{
    extern __shared__ float sm[];
    float* cols = sm;            // [2][64*128]
    float* wds  = sm + 16384;    // [2][4096]

    int hp = blockIdx.x;          // row pair 0..31
    int t  = blockIdx.y;
    int tid = threadIdx.x;
    int cp = tid & 31, spg = tid >> 5;      // GEMM roles
    int sp = tid & 127, chalf = tid >> 7;   // gather roles
    int row = sp >> 6, wpos = sp & 63;
    int h = hp*2 + row;
    int obase = t*HW_ + h*W_ + wpos;

    const float* __restrict__ y1 = g_y1;
    const float* __restrict__ offp = g_off;

    u64 acc0[8], acc1[8];
    #pragma unroll
    for (int i = 0; i < 8; i++) { acc0[i] = 0ull; acc1[i] = 0ull; }

    int gi0, gi1, gi2, gi3;
    float gq0, gq1, gq2, gq3;

    auto compute_idx = [&](int kk, float dh, float dw){
        int kt = kk/9, khh = (kk/3)%3, kww = kk%3;
        int t_in = t - 1 + kt;
        bool t_ok = (t_in >= 0) && (t_in < T_);
        int t_c = min(max(t_in, 0), T_-1);
        float h_s = (float)(h - 1 + khh) + dh;
        float w_s = (float)(wpos - 1 + kww) + dw;
        float h0f = floorf(h_s), w0f = floorf(w_s);
        float fh = h_s - h0f, fw = w_s - w0f;
        int ih0 = (int)h0f, iw0 = (int)w0f, ih1 = ih0+1, iw1 = iw0+1;
        bool okh0 = (ih0 >= 0) && (ih0 < H_), okh1 = (ih1 >= 0) && (ih1 < H_);
        bool okw0 = (iw0 >= 0) && (iw0 < W_), okw1 = (iw1 >= 0) && (iw1 < W_);
        int ih0c = min(max(ih0,0),H_-1), ih1c = min(max(ih1,0),H_-1);
        int iw0c = min(max(iw0,0),W_-1), iw1c = min(max(iw1,0),W_-1);
        int tb = t_c*HW_;
        gi0 = tb + ih0c*W_ + iw0c; gi1 = tb + ih0c*W_ + iw1c;
        gi2 = tb + ih1c*W_ + iw0c; gi3 = tb + ih1c*W_ + iw1c;
        float wh0 = 1.f - fh, wh1 = fh, wv0 = 1.f - fw, wv1 = fw;
        gq0 = (t_ok && okh0 && okw0) ? wh0*wv0 : 0.f;
        gq1 = (t_ok && okh0 && okw1) ? wh0*wv1 : 0.f;
        gq2 = (t_ok && okh1 && okw0) ? wh1*wv0 : 0.f;
        gq3 = (t_ok && okh1 && okw1) ? wh1*wv1 : 0.f;
    };

    auto gemm_range = [&](const float* cbuf, const float* wbuf, int c0, int c1){
        #pragma unroll
        for (int c = c0; c < c1; c++) {
            float2 wv = *reinterpret_cast<const float2*>(&wbuf[c*64 + 2*cp]);
            u64 wp0 = pack2(wv.x, wv.x), wp1 = pack2(wv.y, wv.y);
            const ulonglong2* cp2 =
                reinterpret_cast<const ulonglong2*>(&cbuf[c*128 + spg*16]);
            ulonglong2 q0 = cp2[0], q1 = cp2[1], q2 = cp2[2], q3 = cp2[3];
            fma2(acc0[0], wp0, q0.x); fma2(acc1[0], wp1, q0.x);
            fma2(acc0[1], wp0, q0.y); fma2(acc1[1], wp1, q0.y);
            fma2(acc0[2], wp0, q1.x); fma2(acc1[2], wp1, q1.x);
            fma2(acc0[3], wp0, q1.y); fma2(acc1[3], wp1, q1.y);
            fma2(acc0[4], wp0, q2.x); fma2(acc1[4], wp1, q2.x);
            fma2(acc0[5], wp0, q2.y); fma2(acc1[5], wp1, q2.y);
            fma2(acc0[6], wp0, q3.x); fma2(acc1[6], wp1, q3.x);
            fma2(acc0[7], wp0, q3.y); fma2(acc1[7], wp1, q3.y);
        }
    };

    float vb[16];
    auto issue_chunk = [&](int j){
        #pragma unroll
        for (int q = 0; q < 4; q++) {
            int c = 2*(4*j+q) + chalf;
            const float* p = y1 + c*THW_;
            vb[4*q+0]=__ldg(p+gi0); vb[4*q+1]=__ldg(p+gi1);
            vb[4*q+2]=__ldg(p+gi2); vb[4*q+3]=__ldg(p+gi3);
        }
    };
    auto combine_chunk = [&](int j, float* cnxt){
        #pragma unroll
        for (int q = 0; q < 4; q++) {
            int c = 2*(4*j+q) + chalf;
            float v = fmaf(gq0, vb[4*q+0],
                      fmaf(gq1, vb[4*q+1],
                      fmaf(gq2, vb[4*q+2], gq3*vb[4*q+3])));
            cnxt[c*128 + sp] = v;
        }
    };
    auto cp_wd = [&](int k, float* wbuf){
        const float* src = g_wdt + k*4096 + 16*tid;
        float* dst = wbuf + 16*tid;
        cp16(dst, src); cp16(dst+4, src+4); cp16(dst+8, src+8); cp16(dst+12, src+12);
        cp_commit();
    };

    // ---- prologue: tap 0 gathered inline; weights 0 via cp.async ----
    {
        cp_wd(0, wds);
        float dh = __ldg(&offp[0*THW_ + obase]);
        float dw = __ldg(&offp[1*THW_ + obase]);
        compute_idx(0, dh, dw);
        #pragma unroll 4
        for (int r = 0; r < 32; r++) {
            int c = 2*r + chalf;
            const float* p = y1 + c*THW_;
            float v = fmaf(gq0, __ldg(p+gi0),
                      fmaf(gq1, __ldg(p+gi1),
                      fmaf(gq2, __ldg(p+gi2), gq3*__ldg(p+gi3))));
            cols[c*128 + sp] = v;
        }
    }
    float dh_n = __ldg(&offp[2*THW_ + obase]);   // offsets for tap 1
    float dw_n = __ldg(&offp[3*THW_ + obase]);
    cp_wait0();
    __syncthreads();

    for (int k = 0; k < 27; k++) {
        int cur = k & 1;
        const float* ccur = cols + cur*8192;
        float*       cnxt = cols + (cur^1)*8192;
        const float* wcur = wds + cur*4096;
        float*       wnxt = wds + (cur^1)*4096;

        if (k < 26) cp_wd(k+1, wnxt);           // zero-register weight prefetch

        float dh_nn = 0.f, dw_nn = 0.f;
        if (k < 25) {
            dh_nn = __ldg(&offp[(2*k+4)*THW_ + obase]);
            dw_nn = __ldg(&offp[(2*k+5)*THW_ + obase]);
        }

        if (k < 26) {
            compute_idx(k+1, dh_n, dw_n);
            issue_chunk(0);
            #pragma unroll
            for (int j = 0; j < 8; j++) {
                gemm_range(ccur, wcur, j*8, j*8+8);
                combine_chunk(j, cnxt);
                if (j < 7) issue_chunk(j+1);
            }
        } else {
            gemm_range(ccur, wcur, 0, 64);
        }
        dh_n = dh_nn; dw_n = dw_nn;
        cp_wait0();
        __syncthreads();
    }

    // convert acc: lrelu(acc + bd) + br
    int co0 = 2*cp, co1 = co0 + 1;
    {
        float bd0 = __ldg(&bd[co0]), bd1 = __ldg(&bd[co1]);
        float br0 = __ldg(&br[co0]), br1 = __ldg(&br[co1]);
        #pragma unroll
        for (int p = 0; p < 8; p++) {
            float2 a = unpack2(acc0[p]);
            float v0 = a.x + bd0; v0 = (v0 >= 0.f) ? v0 : 0.01f*v0;
            float v1 = a.y + bd0; v1 = (v1 >= 0.f) ? v1 : 0.01f*v1;
            acc0[p] = pack2(v0 + br0, v1 + br0);
            float2 c2 = unpack2(acc1[p]);
            float u0 = c2.x + bd1; u0 = (u0 >= 0.f) ? u0 : 0.01f*u0;
            float u1 = c2.y + bd1; u1 = (u1 >= 0.f) ? u1 : 0.01f*u1;
            acc1[p] = pack2(u0 + br1, u1 + br1);
        }
    }

    // residual 1x1: stage x tile + Wr via cp.async, one more GEMM pass
    #pragma unroll 4
    for (int r = 0; r < 32; r++) {
        int c = 2*r + chalf;
        cp4(&cols[c*128 + sp], &x[c*THW_ + obase]);
    }
    {
        const float* src = g_wrt + 16*tid;
        float* dst = wds + 16*tid;
        cp16(dst, src); cp16(dst+4, src+4); cp16(dst+8, src+8); cp16(dst+12, src+12);
    }
    cp_commit();
    cp_wait0();
    __syncthreads();
    gemm_range(cols, wds, 0, 64);

    // write out
    int rowp = spg >> 2;
    int wq = (spg & 3) * 16;
    int gbase = t*HW_ + (hp*2 + rowp)*W_ + wq;
    #pragma unroll
    for (int p = 0; p < 8; p++) {
        float2 a = unpack2(acc0[p]);
        *reinterpret_cast<float2*>(&out[co0*THW_ + gbase + 2*p]) = a;
        float2 c2 = unpack2(acc1[p]);
        *reinterpret_cast<float2*>(&out[co1*THW_ + gbase + 2*p]) = c2;
    }
}

// ---------------- launch ----------------
extern "C" void kernel_launch(void* const* d_in, const int* in_sizes, int n_in,
                              void* d_out, int out_size)
{
    const float* x     = (const float*)d_in[0];
    const float* W1    = (const float*)d_in[1];
    const float* b1    = (const float*)d_in[2];
    const float* W_off = (const float*)d_in[3];
    const float* b_off = (const float*)d_in[4];
    const float* Wd    = (const float*)d_in[5];
    const float* bd    = (const float*)d_in[6];
    const float* Wr    = (const float*)d_in[7];
    const float* br    = (const float*)d_in[8];
    float* out = (float*)d_out;
    (void)in_sizes; (void)n_in; (void)out_size;

    const int DSMEM = (16384*2 + 4096*2) * 4;   // 98304 B
    cudaFuncSetAttribute(deform_fused, cudaFuncAttributeMaxDynamicSharedMemorySize, DSMEM);

    dim3 cgrid(8, 8, 8);  // (w-tiles, h-tiles, t)

    prep_weights<<<1312, 256>>>(W1, W_off, Wd, Wr);
    // y1 = lrelu(conv3d(x, W1, b1, pad=1))      -> g_y1
    conv3x3x3<64, true,  false, false><<<cgrid, 256>>>(x, b1);
    // offsets = conv3d(y1, W_off, b_off, pad=1) -> g_off
    conv3x3x3<54, false, true,  true ><<<cgrid, 256>>>(nullptr, b_off);
    // out = lrelu(deform(y1, offsets) + bd) + (Wr*x + br)
    deform_fused<<<dim3(32, 8), 256, DSMEM>>>(x, bd, br, out);
}